// round 3
// baseline (speedup 1.0000x reference)
#include <cuda_runtime.h>
#include <cuda_bf16.h>
#include <cstdint>

#define BB 256
#define SS 512
#define DD 1024
#define TT 17

// ---------------- device scratch (no allocations allowed) ----------------
__device__ float g_eem[(size_t)BB * SS * TT];   // exp(em - rowmax), 8.9 MB
__device__ float g_part_score[512];             // per-block numerator partials
__device__ float g_part_msum[512];              // per-block sum of masked row-maxes
__device__ int   g_part_mcnt[512];              // per-block mask counts
__device__ float g_denom[BB];                   // log partition minus msum offset

__device__ __forceinline__ void fma2(unsigned long long &acc,
                                     unsigned long long a,
                                     unsigned long long b) {
    asm("fma.rn.f32x2 %0, %1, %2, %0;" : "+l"(acc) : "l"(a), "l"(b));
}

// ============================================================
// Kernel 1: emissions GEMM + eem/rowmax + numerator partials
//   grid 512 blocks x 256 threads; 1 row per thread.
//   Software-pipelined: 4 LDG.128 per chunk, double buffered.
// ============================================================
__global__ void __launch_bounds__(256, 3)
emis_kernel(const float* __restrict__ data, const int* __restrict__ labels,
            const int* __restrict__ mask, const float* __restrict__ W,
            const float* __restrict__ bias, const float* __restrict__ start,
            const float* __restrict__ trans)
{
    extern __shared__ float sWf[];  // 17*1024 floats for W + reduction tail
    int tid = threadIdx.x;

    // cooperative load of W [T, D] into shared (float4)
    const float4* W4 = reinterpret_cast<const float4*>(W);
    float4* sW4 = reinterpret_cast<float4*>(sWf);
    for (int i = tid; i < TT * DD / 4; i += 256) sW4[i] = W4[i];
    __syncthreads();

    int row = blockIdx.x * 256 + tid;           // row = b*S + s
    const float4* drow = reinterpret_cast<const float4*>(data + (size_t)row * DD);
    const ulonglong2* sWv = reinterpret_cast<const ulonglong2*>(sWf);

    unsigned long long acc[TT];
    #pragma unroll
    for (int t = 0; t < TT; t++) acc[t] = 0ull;

    // double-buffered pipeline: chunk = 4 float4 (16 k-values)
    float4 bufA[4], bufB[4];

    #pragma unroll
    for (int q = 0; q < 4; q++) bufA[q] = __ldg(drow + q);

    #define PROC(BUF, cbase)                                                    \
        do {                                                                     \
            _Pragma("unroll")                                                    \
            for (int q = 0; q < 4; q++) {                                        \
                unsigned long long dx =                                          \
                    *reinterpret_cast<unsigned long long*>(&BUF[q].x);           \
                unsigned long long dy =                                          \
                    *reinterpret_cast<unsigned long long*>(&BUF[q].z);           \
                _Pragma("unroll")                                                \
                for (int t = 0; t < TT; t++) {                                   \
                    ulonglong2 w = sWv[t * (DD / 4) + (cbase) + q];              \
                    fma2(acc[t], dx, w.x);                                       \
                    fma2(acc[t], dy, w.y);                                       \
                }                                                                \
            }                                                                    \
        } while (0)

    // 64 chunks of 4 float4 each
    #pragma unroll 2
    for (int c = 0; c < 62; c += 2) {
        #pragma unroll
        for (int q = 0; q < 4; q++) bufB[q] = __ldg(drow + (c + 1) * 4 + q);
        PROC(bufA, c * 4);
        #pragma unroll
        for (int q = 0; q < 4; q++) bufA[q] = __ldg(drow + (c + 2) * 4 + q);
        PROC(bufB, (c + 1) * 4);
    }
    #pragma unroll
    for (int q = 0; q < 4; q++) bufB[q] = __ldg(drow + 63 * 4 + q);
    PROC(bufA, 62 * 4);
    PROC(bufB, 63 * 4);
    #undef PROC

    float emv[TT];
    float m = -1e30f;
    #pragma unroll
    for (int t = 0; t < TT; t++) {
        float lo = __uint_as_float((unsigned)(acc[t] & 0xffffffffull));
        float hi = __uint_as_float((unsigned)(acc[t] >> 32));
        emv[t] = lo + hi + __ldg(bias + t);
        m = fmaxf(m, emv[t]);
    }

    float* eout = g_eem + (size_t)row * TT;
    #pragma unroll
    for (int t = 0; t < TT; t++) eout[t] = __expf(emv[t] - m);

    // ---- numerator contribution for this (b, s) ----
    int s   = row & (SS - 1);
    int lab = __ldg(labels + row);
    float em_lab = 0.0f;
    #pragma unroll
    for (int t = 0; t < TT; t++) em_lab = (lab == t) ? emv[t] : em_lab;

    float mk = (__ldg(mask + row) != 0) ? 1.0f : 0.0f;
    float contrib;
    if (s == 0) {
        contrib = __ldg(start + lab) + em_lab;       // always included
    } else {
        int prev = __ldg(labels + row - 1);
        contrib = mk * (__ldg(trans + prev * TT + lab) + em_lab);
    }
    float msum_t = mk * m;
    int   mcnt_t = (mk > 0.0f) ? 1 : 0;

    // ---- block reduction (deterministic, no atomics) ----
    const unsigned FULL = 0xffffffffu;
    #pragma unroll
    for (int off = 16; off; off >>= 1) {
        contrib += __shfl_xor_sync(FULL, contrib, off);
        msum_t  += __shfl_xor_sync(FULL, msum_t, off);
        mcnt_t  += __shfl_xor_sync(FULL, mcnt_t, off);
    }
    float* red = sWf + TT * DD;   // 24-slot tail region
    int wid = tid >> 5;
    if ((tid & 31) == 0) {
        red[wid]     = contrib;
        red[8 + wid] = msum_t;
        reinterpret_cast<int*>(red)[16 + wid] = mcnt_t;
    }
    __syncthreads();
    if (tid == 0) {
        float sc = 0.0f, sm = 0.0f; int cn = 0;
        #pragma unroll
        for (int w = 0; w < 8; w++) {
            sc += red[w];
            sm += red[8 + w];
            cn += reinterpret_cast<int*>(red)[16 + w];
        }
        g_part_score[blockIdx.x] = sc;
        g_part_msum[blockIdx.x]  = sm;
        g_part_mcnt[blockIdx.x]  = cn;
    }
}

// ============================================================
// Kernel 2: CRF forward recurrence (linear domain, lazy renorm)
//   128 blocks x 64 threads = 256 warps, 1 warp per batch
// ============================================================
__global__ void __launch_bounds__(64)
crf_kernel(const float* __restrict__ trans, const float* __restrict__ start,
           const float* __restrict__ endt, const int* __restrict__ mask)
{
    const unsigned FULL = 0xffffffffu;
    int b = blockIdx.x * 2 + (threadIdx.x >> 5);
    int j = threadIdx.x & 31;
    bool act = (j < TT);

    // E[i] = exp(transitions[i][j]) held in registers (column j)
    float Ecol[TT];
    #pragma unroll
    for (int i = 0; i < TT; i++)
        Ecol[i] = act ? __expf(__ldg(trans + i * TT + j)) : 0.0f;
    float eend = act ? __expf(__ldg(endt + j)) : 0.0f;

    const float* eb = g_eem + (size_t)b * (SS * TT);
    const int4* mb = reinterpret_cast<const int4*>(mask + b * SS);

    float bufA[8], bufB[8];
    int   mA[8],  mB[8];

    #pragma unroll
    for (int d = 0; d < 8; d++)
        bufA[d] = act ? __ldg(eb + d * TT + j) : 0.0f;
    {
        int4 a = __ldg(mb + 0), c = __ldg(mb + 1);
        mA[0]=a.x; mA[1]=a.y; mA[2]=a.z; mA[3]=a.w;
        mA[4]=c.x; mA[5]=c.y; mA[6]=c.z; mA[7]=c.w;
    }

    // step 0 init: p = eem0 * exp(start); row-max offsets live in msum
    float p = act ? bufA[0] * __expf(__ldg(start + j)) : 0.0f;
    float C = 0.0f;
    float r  = __shfl_sync(FULL, p, 0);
    float sc = __fdividef(1.0f, r);
    float lr = __logf(r);

    auto step = [&](float eemv, int mkv) {
        if (mkv != 0) {  // warp-uniform
            float a[4] = {0.f, 0.f, 0.f, 0.f};
            #pragma unroll
            for (int i = 0; i < TT; i++)
                a[i & 3] = fmaf(__shfl_sync(FULL, p, i), Ecol[i], a[i & 3]);
            float q = (a[0] + a[1]) + (a[2] + a[3]);
            p = q * (eemv * sc);   // apply previous step's scale lazily
            C += lr;
            r  = __shfl_sync(FULL, p, 0);
            sc = __fdividef(1.0f, r);
            lr = __logf(r);
        }
    };

    #define PREFETCH(cidx, BUF, MARR)                                          \
        do {                                                                    \
            _Pragma("unroll")                                                   \
            for (int d = 0; d < 8; d++)                                         \
                BUF[d] = act ? __ldg(eb + ((cidx) * 8 + d) * TT + j) : 0.0f;    \
            int4 _a = __ldg(mb + 2 * (cidx)), _c = __ldg(mb + 2 * (cidx) + 1);  \
            MARR[0]=_a.x; MARR[1]=_a.y; MARR[2]=_a.z; MARR[3]=_a.w;             \
            MARR[4]=_c.x; MARR[5]=_c.y; MARR[6]=_c.z; MARR[7]=_c.w;             \
        } while (0)

    #define PROCESS(BUF, MARR)                                                  \
        do {                                                                    \
            _Pragma("unroll")                                                   \
            for (int d = 0; d < 8; d++) step(BUF[d], MARR[d]);                  \
        } while (0)

    // prefetch chunk 1, process chunk 0 steps 1..7
    PREFETCH(1, bufB, mB);
    #pragma unroll
    for (int d = 1; d < 8; d++) step(bufA[d], mA[d]);

    // main: chunks 1..62 double-buffered, chunk 63 tail
    for (int cc = 1; cc < 63; cc += 2) {
        PREFETCH(cc + 1, bufA, mA);
        PROCESS(bufB, mB);
        PREFETCH(cc + 2, bufB, mB);
        PROCESS(bufA, mA);
    }
    PROCESS(bufB, mB);

    // denom (minus msum offset) = C + log(sum_j p_j * exp(end_j))
    float term = p * eend;   // lanes >= 17 contribute 0
    #pragma unroll
    for (int off = 16; off; off >>= 1)
        term += __shfl_xor_sync(FULL, term, off);
    if (j == 0) g_denom[b] = C + __logf(term);

    #undef PREFETCH
    #undef PROCESS
}

// ============================================================
// Kernel 3: finalize  out = -mean(score - denom)
// ============================================================
__global__ void __launch_bounds__(256)
fin_kernel(const int* __restrict__ labels, const float* __restrict__ endt,
           float* __restrict__ out)
{
    __shared__ float sred[256];
    int b = threadIdx.x;
    int cnt  = g_part_mcnt[2 * b] + g_part_mcnt[2 * b + 1];
    int lt   = __ldg(labels + b * SS + (cnt - 1));
    float score = g_part_score[2 * b] + g_part_score[2 * b + 1] + __ldg(endt + lt);
    float denom = g_denom[b] + g_part_msum[2 * b] + g_part_msum[2 * b + 1];
    sred[b] = score - denom;
    __syncthreads();
    #pragma unroll
    for (int off = 128; off; off >>= 1) {
        if (b < off) sred[b] += sred[b + off];
        __syncthreads();
    }
    if (b == 0) out[0] = -sred[0] * (1.0f / BB);
}

// ============================================================
extern "C" void kernel_launch(void* const* d_in, const int* in_sizes, int n_in,
                              void* d_out, int out_size)
{
    const float* data   = (const float*)d_in[0];
    const int*   labels = (const int*)d_in[1];
    const int*   mask   = (const int*)d_in[2];
    const float* W      = (const float*)d_in[3];
    const float* bias   = (const float*)d_in[4];
    const float* start  = (const float*)d_in[5];
    const float* endt   = (const float*)d_in[6];
    const float* trans  = (const float*)d_in[7];

    const int smem = TT * DD * 4 + 128;   // 69760 bytes
    cudaFuncSetAttribute(emis_kernel,
                         cudaFuncAttributeMaxDynamicSharedMemorySize, smem);

    emis_kernel<<<512, 256, smem>>>(data, labels, mask, W, bias, start, trans);
    crf_kernel<<<BB / 2, 64>>>(trans, start, endt, mask);
    fin_kernel<<<1, 256>>>(labels, endt, (float*)d_out);
}

// round 4
// speedup vs baseline: 2.3622x; 2.3622x over previous
#include <cuda_runtime.h>
#include <cuda_bf16.h>
#include <cstdint>

#define BB 256
#define SS 512
#define DD 1024
#define TT 17
#define EST 20   // padded eem row stride (16B-aligned rows)

// ---------------- device scratch (no allocations allowed) ----------------
__device__ float g_eem[(size_t)BB * SS * EST];  // exp(em - rowmax), 10.5 MB
__device__ float g_part_score[BB];              // per-batch numerator partials
__device__ float g_part_msum[BB];               // per-batch sum of masked row-maxes
__device__ int   g_part_mcnt[BB];               // per-batch mask counts
__device__ float g_denom[BB];                   // log partition minus msum offset

__device__ __forceinline__ void fma2(unsigned long long &acc,
                                     unsigned long long a,
                                     unsigned long long b) {
    asm("fma.rn.f32x2 %0, %1, %2, %0;" : "+l"(acc) : "l"(a), "l"(b));
}

// ============================================================
// Kernel 1: emissions GEMM + eem/rowmax + numerator partials
//   grid 256 blocks x 128 threads; 4 rows per thread (one batch per block)
//   W staged in shared; each W quad (LDS.128) feeds 8 FFMA2s.
// ============================================================
__global__ void __launch_bounds__(128, 2)
emis_kernel(const float* __restrict__ data, const int* __restrict__ labels,
            const int* __restrict__ mask, const float* __restrict__ W,
            const float* __restrict__ bias, const float* __restrict__ start,
            const float* __restrict__ trans)
{
    extern __shared__ float sWf[];  // 17*1024 floats for W + reduction tail
    const int tid = threadIdx.x;
    const int b   = blockIdx.x;

    // cooperative load of W [T, D] into shared (float4)
    const float4* W4 = reinterpret_cast<const float4*>(W);
    float4* sW4 = reinterpret_cast<float4*>(sWf);
    #pragma unroll 2
    for (int i = tid; i < TT * DD / 4; i += 128) sW4[i] = W4[i];
    __syncthreads();

    const ulonglong2* sWv = reinterpret_cast<const ulonglong2*>(sWf);

    // 4 rows per thread: s = tid + r*128, row = b*512 + s
    const float4* drow[4];
    #pragma unroll
    for (int r = 0; r < 4; r++)
        drow[r] = reinterpret_cast<const float4*>(
            data + (size_t)(b * SS + tid + r * 128) * DD);

    unsigned long long acc[4][TT];
    #pragma unroll
    for (int r = 0; r < 4; r++)
        #pragma unroll
        for (int t = 0; t < TT; t++) acc[r][t] = 0ull;

    float4 bufA[4], bufB[4];

    #define FETCH(BUF, KK)                                                     \
        do {                                                                    \
            _Pragma("unroll")                                                   \
            for (int r = 0; r < 4; r++) BUF[r] = __ldg(drow[r] + (KK));         \
        } while (0)

    #define PROC(BUF, KK)                                                      \
        do {                                                                    \
            unsigned long long dx[4], dy[4];                                    \
            _Pragma("unroll")                                                   \
            for (int r = 0; r < 4; r++) {                                       \
                dx[r] = *reinterpret_cast<unsigned long long*>(&BUF[r].x);      \
                dy[r] = *reinterpret_cast<unsigned long long*>(&BUF[r].z);      \
            }                                                                   \
            _Pragma("unroll")                                                   \
            for (int t = 0; t < TT; t++) {                                      \
                ulonglong2 w = sWv[t * (DD / 4) + (KK)];                        \
                _Pragma("unroll")                                               \
                for (int r = 0; r < 4; r++) {                                   \
                    fma2(acc[r][t], dx[r], w.x);                                \
                    fma2(acc[r][t], dy[r], w.y);                                \
                }                                                               \
            }                                                                   \
        } while (0)

    FETCH(bufA, 0);
    #pragma unroll 1
    for (int kk = 0; kk < 254; kk += 2) {
        FETCH(bufB, kk + 1);
        PROC(bufA, kk);
        FETCH(bufA, kk + 2);
        PROC(bufB, kk + 1);
    }
    FETCH(bufB, 255);
    PROC(bufA, 254);
    PROC(bufB, 255);
    #undef FETCH
    #undef PROC

    // ---- epilogue: per-row max/exp/store + numerator accumulation ----
    float contrib = 0.0f, msum_t = 0.0f;
    int mcnt_t = 0;

    #pragma unroll
    for (int r = 0; r < 4; r++) {
        int s   = tid + r * 128;
        int row = b * SS + s;

        float emv[TT];
        float m = -1e30f;
        #pragma unroll
        for (int t = 0; t < TT; t++) {
            float lo = __uint_as_float((unsigned)(acc[r][t] & 0xffffffffull));
            float hi = __uint_as_float((unsigned)(acc[r][t] >> 32));
            emv[t] = lo + hi + __ldg(bias + t);
            m = fmaxf(m, emv[t]);
        }

        float e[TT];
        #pragma unroll
        for (int t = 0; t < TT; t++) e[t] = __expf(emv[t] - m);

        float4* o4 = reinterpret_cast<float4*>(g_eem + (size_t)row * EST);
        o4[0] = make_float4(e[0],  e[1],  e[2],  e[3]);
        o4[1] = make_float4(e[4],  e[5],  e[6],  e[7]);
        o4[2] = make_float4(e[8],  e[9],  e[10], e[11]);
        o4[3] = make_float4(e[12], e[13], e[14], e[15]);
        o4[4] = make_float4(e[16], 0.0f,  0.0f,  0.0f);

        int lab = __ldg(labels + row);
        float em_lab = 0.0f;
        #pragma unroll
        for (int t = 0; t < TT; t++) em_lab = (lab == t) ? emv[t] : em_lab;

        float mk = (__ldg(mask + row) != 0) ? 1.0f : 0.0f;
        if (s == 0) {
            contrib += __ldg(start + lab) + em_lab;   // always included
        } else {
            int prev = __ldg(labels + row - 1);
            contrib += mk * (__ldg(trans + prev * TT + lab) + em_lab);
        }
        msum_t += mk * m;
        mcnt_t += (mk > 0.0f) ? 1 : 0;
    }

    // ---- block reduction (deterministic, no atomics); 4 warps ----
    const unsigned FULL = 0xffffffffu;
    #pragma unroll
    for (int off = 16; off; off >>= 1) {
        contrib += __shfl_xor_sync(FULL, contrib, off);
        msum_t  += __shfl_xor_sync(FULL, msum_t, off);
        mcnt_t  += __shfl_xor_sync(FULL, mcnt_t, off);
    }
    float* red = sWf + TT * DD;   // 12-slot tail region
    int wid = tid >> 5;
    if ((tid & 31) == 0) {
        red[wid]     = contrib;
        red[4 + wid] = msum_t;
        reinterpret_cast<int*>(red)[8 + wid] = mcnt_t;
    }
    __syncthreads();
    if (tid == 0) {
        float sc = 0.0f, sm = 0.0f; int cn = 0;
        #pragma unroll
        for (int w = 0; w < 4; w++) {
            sc += red[w];
            sm += red[4 + w];
            cn += reinterpret_cast<int*>(red)[8 + w];
        }
        g_part_score[b] = sc;
        g_part_msum[b]  = sm;
        g_part_mcnt[b]  = cn;
    }
}

// ============================================================
// Kernel 2: CRF forward recurrence (linear domain, lazy renorm)
//   128 blocks x 64 threads = 256 warps, 1 warp per batch
// ============================================================
__global__ void __launch_bounds__(64)
crf_kernel(const float* __restrict__ trans, const float* __restrict__ start,
           const float* __restrict__ endt, const int* __restrict__ mask)
{
    const unsigned FULL = 0xffffffffu;
    int b = blockIdx.x * 2 + (threadIdx.x >> 5);
    int j = threadIdx.x & 31;
    bool act = (j < TT);

    // E[i] = exp(transitions[i][j]) held in registers (column j)
    float Ecol[TT];
    #pragma unroll
    for (int i = 0; i < TT; i++)
        Ecol[i] = act ? __expf(__ldg(trans + i * TT + j)) : 0.0f;
    float eend = act ? __expf(__ldg(endt + j)) : 0.0f;

    const float* eb = g_eem + (size_t)b * (SS * EST);
    const int4* mb = reinterpret_cast<const int4*>(mask + b * SS);

    float bufA[8], bufB[8];
    int   mA[8],  mB[8];

    #pragma unroll
    for (int d = 0; d < 8; d++)
        bufA[d] = act ? __ldg(eb + d * EST + j) : 0.0f;
    {
        int4 a = __ldg(mb + 0), c = __ldg(mb + 1);
        mA[0]=a.x; mA[1]=a.y; mA[2]=a.z; mA[3]=a.w;
        mA[4]=c.x; mA[5]=c.y; mA[6]=c.z; mA[7]=c.w;
    }

    // step 0 init: p = eem0 * exp(start); row-max offsets live in msum
    float p = act ? bufA[0] * __expf(__ldg(start + j)) : 0.0f;
    float C = 0.0f;
    float r  = __shfl_sync(FULL, p, 0);
    float sc = __fdividef(1.0f, r);
    float lr = __logf(r);

    auto step = [&](float eemv, int mkv) {
        if (mkv != 0) {  // warp-uniform
            float a[4] = {0.f, 0.f, 0.f, 0.f};
            #pragma unroll
            for (int i = 0; i < TT; i++)
                a[i & 3] = fmaf(__shfl_sync(FULL, p, i), Ecol[i], a[i & 3]);
            float q = (a[0] + a[1]) + (a[2] + a[3]);
            p = q * (eemv * sc);   // apply previous step's scale lazily
            C += lr;
            r  = __shfl_sync(FULL, p, 0);
            sc = __fdividef(1.0f, r);
            lr = __logf(r);
        }
    };

    #define PREFETCH(cidx, BUF, MARR)                                          \
        do {                                                                    \
            _Pragma("unroll")                                                   \
            for (int d = 0; d < 8; d++)                                         \
                BUF[d] = act ? __ldg(eb + ((cidx) * 8 + d) * EST + j) : 0.0f;   \
            int4 _a = __ldg(mb + 2 * (cidx)), _c = __ldg(mb + 2 * (cidx) + 1);  \
            MARR[0]=_a.x; MARR[1]=_a.y; MARR[2]=_a.z; MARR[3]=_a.w;             \
            MARR[4]=_c.x; MARR[5]=_c.y; MARR[6]=_c.z; MARR[7]=_c.w;             \
        } while (0)

    #define PROCESS(BUF, MARR)                                                  \
        do {                                                                    \
            _Pragma("unroll")                                                   \
            for (int d = 0; d < 8; d++) step(BUF[d], MARR[d]);                  \
        } while (0)

    // prefetch chunk 1, process chunk 0 steps 1..7
    PREFETCH(1, bufB, mB);
    #pragma unroll
    for (int d = 1; d < 8; d++) step(bufA[d], mA[d]);

    // main: chunks 1..62 double-buffered, chunk 63 tail
    for (int cc = 1; cc < 63; cc += 2) {
        PREFETCH(cc + 1, bufA, mA);
        PROCESS(bufB, mB);
        PREFETCH(cc + 2, bufB, mB);
        PROCESS(bufA, mA);
    }
    PROCESS(bufB, mB);

    // denom (minus msum offset) = C + log(sum_j p_j * exp(end_j))
    float term = p * eend;   // lanes >= 17 contribute 0
    #pragma unroll
    for (int off = 16; off; off >>= 1)
        term += __shfl_xor_sync(FULL, term, off);
    if (j == 0) g_denom[b] = C + __logf(term);

    #undef PREFETCH
    #undef PROCESS
}

// ============================================================
// Kernel 3: finalize  out = -mean(score - denom)
// ============================================================
__global__ void __launch_bounds__(256)
fin_kernel(const int* __restrict__ labels, const float* __restrict__ endt,
           float* __restrict__ out)
{
    __shared__ float sred[256];
    int b = threadIdx.x;
    int cnt  = g_part_mcnt[b];
    int lt   = __ldg(labels + b * SS + (cnt - 1));
    float score = g_part_score[b] + __ldg(endt + lt);
    float denom = g_denom[b] + g_part_msum[b];
    sred[b] = score - denom;
    __syncthreads();
    #pragma unroll
    for (int off = 128; off; off >>= 1) {
        if (b < off) sred[b] += sred[b + off];
        __syncthreads();
    }
    if (b == 0) out[0] = -sred[0] * (1.0f / BB);
}

// ============================================================
extern "C" void kernel_launch(void* const* d_in, const int* in_sizes, int n_in,
                              void* d_out, int out_size)
{
    const float* data   = (const float*)d_in[0];
    const int*   labels = (const int*)d_in[1];
    const int*   mask   = (const int*)d_in[2];
    const float* W      = (const float*)d_in[3];
    const float* bias   = (const float*)d_in[4];
    const float* start  = (const float*)d_in[5];
    const float* endt   = (const float*)d_in[6];
    const float* trans  = (const float*)d_in[7];

    const int smem = TT * DD * 4 + 128;   // 69760 bytes
    cudaFuncSetAttribute(emis_kernel,
                         cudaFuncAttributeMaxDynamicSharedMemorySize, smem);

    emis_kernel<<<BB, 128, smem>>>(data, labels, mask, W, bias, start, trans);
    crf_kernel<<<BB / 2, 64>>>(trans, start, endt, mask);
    fin_kernel<<<1, 256>>>(labels, endt, (float*)d_out);
}